// round 4
// baseline (speedup 1.0000x reference)
#include <cuda_runtime.h>
#include <math.h>

// Problem constants (fixed by setup_inputs)
#define NPTS  4096
#define BB    4
#define NPER  1024
#define LL    16
#define FV    256
#define FLANG 768
#define FF    128
#define KNN   16

// ---------------- scratch (device globals; no allocations allowed) -----------
__device__ float g_feats[NPTS * FF];      // encoded point features
__device__ float g_hl[BB * LL * FF];      // lang hidden pre-BN
__device__ float g_hr[BB * LL * FF];      // lang hidden post-BN+ReLU
__device__ float g_lang[BB * LL * FF];    // encoded lang features
__device__ float g_atten[NPTS * LL];      // per-point/token logits
__device__ int   g_knn[NPTS * KNN];       // neighbor ids (global)

// ---------------- kernel 1: feat_encoder  (Linear->LN->ReLU->Linear) ---------
__global__ __launch_bounds__(FF) void k_feat(
    const float* __restrict__ X, const float* __restrict__ W1,
    const float* __restrict__ b1, const float* __restrict__ lng,
    const float* __restrict__ lnb, const float* __restrict__ W2,
    const float* __restrict__ b2)
{
    int n = blockIdx.x, f = threadIdx.x;
    __shared__ float s_in[FV];
    __shared__ float s_h[FF];
    __shared__ float s_red[FF];

    s_in[f]       = X[n * FV + f];
    s_in[f + FF]  = X[n * FV + FF + f];
    __syncthreads();

    float acc = b1[f];
    #pragma unroll 8
    for (int v = 0; v < FV; v++) acc = fmaf(s_in[v], W1[v * FF + f], acc);

    // LayerNorm over 128 features (biased var, eps 1e-5)
    s_red[f] = acc; __syncthreads();
    for (int s = 64; s > 0; s >>= 1) { if (f < s) s_red[f] += s_red[f + s]; __syncthreads(); }
    float mean = s_red[0] * (1.f / FF);
    __syncthreads();
    float d = acc - mean;
    s_red[f] = d * d; __syncthreads();
    for (int s = 64; s > 0; s >>= 1) { if (f < s) s_red[f] += s_red[f + s]; __syncthreads(); }
    float var = s_red[0] * (1.f / FF);

    float h = d / sqrtf(var + 1e-5f) * lng[f] + lnb[f];
    s_h[f] = fmaxf(h, 0.f);
    __syncthreads();

    float o = b2[f];
    #pragma unroll 8
    for (int c = 0; c < FF; c++) o = fmaf(s_h[c], W2[c * FF + f], o);
    g_feats[n * FF + f] = o;
}

// ---------------- kernel 2a: lang first linear -------------------------------
__global__ __launch_bounds__(FF) void k_langA(
    const float* __restrict__ LFT, const float* __restrict__ Wl1,
    const float* __restrict__ bl1)
{
    int r = blockIdx.x, f = threadIdx.x;
    __shared__ float s_in[FLANG];
    for (int t = f; t < FLANG; t += FF) s_in[t] = LFT[r * FLANG + t];
    __syncthreads();
    float acc = bl1[f];
    #pragma unroll 8
    for (int v = 0; v < FLANG; v++) acc = fmaf(s_in[v], Wl1[v * FF + f], acc);
    g_hl[r * FF + f] = acc;
}

// ---------------- kernel 2b: BatchNorm (over 64 rows) + ReLU -----------------
__global__ __launch_bounds__(FF) void k_langB(
    const float* __restrict__ bng, const float* __restrict__ bnb)
{
    int f = threadIdx.x;
    const int R = BB * LL;
    float m = 0.f;
    for (int r = 0; r < R; r++) m += g_hl[r * FF + f];
    m *= (1.f / R);
    float v = 0.f;
    for (int r = 0; r < R; r++) { float d = g_hl[r * FF + f] - m; v += d * d; }
    v *= (1.f / R);
    float is = 1.f / sqrtf(v + 1e-5f);
    float gg = bng[f], bb = bnb[f];
    for (int r = 0; r < R; r++) {
        float h = (g_hl[r * FF + f] - m) * is * gg + bb;
        g_hr[r * FF + f] = fmaxf(h, 0.f);
    }
}

// ---------------- kernel 2c: lang second linear ------------------------------
__global__ __launch_bounds__(FF) void k_langC(
    const float* __restrict__ Wl2, const float* __restrict__ bl2)
{
    int r = blockIdx.x, f = threadIdx.x;
    __shared__ float s_h[FF];
    s_h[f] = g_hr[r * FF + f];
    __syncthreads();
    float o = bl2[f];
    #pragma unroll 8
    for (int c = 0; c < FF; c++) o = fmaf(s_h[c], Wl2[c * FF + f], o);
    g_lang[r * FF + f] = o;
}

// ---------------- kernel 3: attention logits  (warp per (n,l)) ---------------
__global__ __launch_bounds__(256) void k_atten(const int* __restrict__ bidx)
{
    int wid  = (blockIdx.x * blockDim.x + threadIdx.x) >> 5;
    int lane = threadIdx.x & 31;
    int n = wid >> 4, l = wid & 15;
    int b = bidx[n];
    const float* fp = g_feats + n * FF;
    const float* lp = g_lang + (b * LL + l) * FF;
    float s = 0.f;
    #pragma unroll
    for (int t = lane; t < FF; t += 32) s = fmaf(fp[t], lp[t], s);
    #pragma unroll
    for (int o = 16; o; o >>= 1) s += __shfl_xor_sync(0xffffffffu, s, o);
    if (lane == 0) g_atten[n * LL + l] = s;
}

// ---------------- kernel 4: batched kNN (thread per query) -------------------
__global__ __launch_bounds__(128) void k_knn(const float* __restrict__ xyz)
{
    __shared__ float s_x[NPER], s_y[NPER], s_z[NPER];
    int tid = threadIdx.x;
    int bq  = blockIdx.x >> 3;                  // batch (8 blocks per batch)
    int lq  = (blockIdx.x & 7) * 128 + tid;     // local query id

    for (int t = tid; t < NPER; t += 128) {
        int g = (bq * NPER + t) * 3;
        s_x[t] = xyz[g]; s_y[t] = xyz[g + 1]; s_z[t] = xyz[g + 2];
    }
    __syncthreads();

    float qx = s_x[lq], qy = s_y[lq], qz = s_z[lq];
    float bd[KNN]; int bi[KNN];
    #pragma unroll
    for (int t = 0; t < KNN; t++) { bd[t] = 3.4e38f; bi[t] = 0; }

    for (int j = 0; j < NPER; j++) {
        float dx = qx - s_x[j], dy = qy - s_y[j], dz = qz - s_z[j];
        float d2 = dx * dx + dy * dy + dz * dz;
        if (d2 < bd[KNN - 1]) {
            float cd = d2; int ci = j;
            #pragma unroll
            for (int t = 0; t < KNN; t++) {
                if (cd < bd[t]) {
                    float td = bd[t]; int ti = bi[t];
                    bd[t] = cd; bi[t] = ci; cd = td; ci = ti;
                }
            }
        }
    }
    int base = bq * NPER;
    #pragma unroll
    for (int t = 0; t < KNN; t++) g_knn[(base + lq) * KNN + t] = base + bi[t];
}

// ---------------- kernel 5: edges: softmax + rel MLP + message + sum ---------
__global__ __launch_bounds__(FF) void k_edge(
    const float* __restrict__ xyz, const int* __restrict__ bidx,
    const float* __restrict__ mask,
    const float* __restrict__ Wr1, const float* __restrict__ br1,
    const float* __restrict__ Wr2, const float* __restrict__ br2,
    float* __restrict__ out)
{
    int i = blockIdx.x, f = threadIdx.x;
    __shared__ int   s_nb[KNN];
    __shared__ float s_a[KNN][LL];     // attention weights
    __shared__ float s_hid[KNN][64];   // rel MLP hidden
    __shared__ float s_geo[KNN][10];   // geometric edge features

    if (f < KNN) s_nb[f] = g_knn[i * KNN + f];
    __syncthreads();

    // load neighbor logits: 256 values, 2 per thread
    {
        int j = f >> 4, l = f & 15;
        s_a[j][l] = g_atten[s_nb[j] * LL + l];
        int f2 = f + 128; j = f2 >> 4; l = f2 & 15;
        s_a[j][l] = g_atten[s_nb[j] * LL + l];
    }
    __syncthreads();

    // phase A: per-l softmax over the 16 neighbors, * mask[i,l]
    if (f < LL) {
        int l = f;
        float m = -3.4e38f;
        #pragma unroll
        for (int j = 0; j < KNN; j++) m = fmaxf(m, s_a[j][l]);
        float e[KNN]; float sum = 0.f;
        #pragma unroll
        for (int j = 0; j < KNN; j++) { e[j] = expf(s_a[j][l] - m); sum += e[j]; }
        float scale = mask[i * LL + l] / sum;
        #pragma unroll
        for (int j = 0; j < KNN; j++) s_a[j][l] = e[j] * scale;
    }
    __syncthreads();

    // phase B: per-edge renormalization over l + geometric features
    if (f < KNN) {
        int j = f;
        float s = 0.f;
        #pragma unroll
        for (int l = 0; l < LL; l++) s += s_a[j][l];
        float inv = 1.f / (s + 1e-7f);
        #pragma unroll
        for (int l = 0; l < LL; l++) s_a[j][l] *= inv;

        int nj = s_nb[j];
        float xi0 = xyz[i * 3], xi1 = xyz[i * 3 + 1], xi2 = xyz[i * 3 + 2];
        float xj0 = xyz[nj * 3], xj1 = xyz[nj * 3 + 1], xj2 = xyz[nj * 3 + 2];
        float d0 = xi0 - xj0, d1 = xi1 - xj1, d2 = xi2 - xj2;
        float nr = sqrtf(d0 * d0 + d1 * d1 + d2 * d2 + 1e-12f);
        s_geo[j][0] = xi0; s_geo[j][1] = xi1; s_geo[j][2] = xi2;
        s_geo[j][3] = xj0; s_geo[j][4] = xj1; s_geo[j][5] = xj2;
        s_geo[j][6] = d0;  s_geo[j][7] = d1;  s_geo[j][8] = d2;
        s_geo[j][9] = nr;
    }
    __syncthreads();

    // rel MLP hidden layer: 128 threads = 2 neighbors x 64 hidden units
    {
        int h = f & 63, jh = f >> 6;
        #pragma unroll
        for (int it = 0; it < 8; it++) {
            int j = it * 2 + jh;
            float acc = br1[h];
            #pragma unroll
            for (int d = 0; d < 10; d++) acc = fmaf(s_geo[j][d], Wr1[d * 64 + h], acc);
            s_hid[j][h] = fmaxf(acc, 0.f);
        }
    }
    __syncthreads();

    // rel MLP output: hoist Wr2 over neighbors (16 register accumulators)
    float ew[KNN];
    float brf = br2[f];
    #pragma unroll
    for (int j = 0; j < KNN; j++) ew[j] = brf;
    for (int h = 0; h < 64; h++) {
        float w = Wr2[h * FF + f];
        #pragma unroll
        for (int j = 0; j < KNN; j++) ew[j] = fmaf(s_hid[j][h], w, ew[j]);
    }

    // ctx = att @ lang_b : hoist lang over neighbors
    float ctx[KNN];
    #pragma unroll
    for (int j = 0; j < KNN; j++) ctx[j] = 0.f;
    int b = bidx[i];
    const float* lb = g_lang + b * LL * FF;
    #pragma unroll
    for (int l = 0; l < LL; l++) {
        float w = lb[l * FF + f];
        #pragma unroll
        for (int j = 0; j < KNN; j++) ctx[j] = fmaf(s_a[j][l], w, ctx[j]);
    }

    // msg = feats[col] * ctx * ew ; sum over neighbors ; residual add
    float o = g_feats[i * FF + f];
    #pragma unroll
    for (int j = 0; j < KNN; j++)
        o += g_feats[s_nb[j] * FF + f] * ctx[j] * ew[j];
    out[i * FF + f] = o;
}

// ---------------- launch ------------------------------------------------------
extern "C" void kernel_launch(void* const* d_in, const int* in_sizes, int n_in,
                              void* d_out, int out_size)
{
    const float* xyz   = (const float*)d_in[0];
    const int*   bidx  = (const int*)  d_in[1];
    const float* feats = (const float*)d_in[2];
    const float* lft   = (const float*)d_in[3];
    const float* mask  = (const float*)d_in[4];
    const float* W1    = (const float*)d_in[5];
    const float* b1    = (const float*)d_in[6];
    const float* lng   = (const float*)d_in[7];
    const float* lnb   = (const float*)d_in[8];
    const float* W2    = (const float*)d_in[9];
    const float* b2    = (const float*)d_in[10];
    const float* Wl1   = (const float*)d_in[11];
    const float* bl1   = (const float*)d_in[12];
    const float* bng   = (const float*)d_in[13];
    const float* bnb   = (const float*)d_in[14];
    const float* Wl2   = (const float*)d_in[15];
    const float* bl2   = (const float*)d_in[16];
    const float* Wr1   = (const float*)d_in[17];
    const float* br1   = (const float*)d_in[18];
    const float* Wr2   = (const float*)d_in[19];
    const float* br2   = (const float*)d_in[20];
    float* out = (float*)d_out;

    k_feat<<<NPTS, FF>>>(feats, W1, b1, lng, lnb, W2, b2);
    k_langA<<<BB * LL, FF>>>(lft, Wl1, bl1);
    k_langB<<<1, FF>>>(bng, bnb);
    k_langC<<<BB * LL, FF>>>(Wl2, bl2);
    k_atten<<<(NPTS * LL) / 8, 256>>>(bidx);
    k_knn<<<NPTS / 128, 128>>>(xyz);
    k_edge<<<NPTS, FF>>>(xyz, bidx, mask, Wr1, br1, Wr2, br2, out);
}

// round 7
// speedup vs baseline: 2.4650x; 2.4650x over previous
#include <cuda_runtime.h>
#include <math.h>

// Problem constants (fixed by setup_inputs)
#define NPTS  4096
#define BB    4
#define NPER  1024
#define LL    16
#define FV    256
#define FLANG 768
#define FF    128
#define KNN   16

// ---------------- scratch (device globals; no allocations allowed) -----------
__device__ __align__(16) float g_feats[NPTS * FF];   // encoded point features
__device__ __align__(16) float g_hl[BB * LL * FF];   // lang hidden pre-BN
__device__ __align__(16) float g_lang[BB * LL * FF]; // encoded lang features
__device__ __align__(16) float g_atten[NPTS * LL];   // per-point/token logits
__device__ int   g_knn[NPTS * KNN];                  // neighbor ids (global)

// ---------------- kernel 1: lang first linear (vectorized, v-split) ----------
__global__ __launch_bounds__(128) void k_langA(
    const float* __restrict__ LFT, const float* __restrict__ Wl1,
    const float* __restrict__ bl1)
{
    int r = blockIdx.x, tid = threadIdx.x;
    __shared__ __align__(16) float s_in[FLANG];
    __shared__ __align__(16) float4 s_part[4][32];

    for (int t = tid; t < FLANG; t += 128) s_in[t] = LFT[r * FLANG + t];
    __syncthreads();

    int fq = tid & 31, vs = tid >> 5;        // f-quad, v-slice
    float4 acc = make_float4(0.f, 0.f, 0.f, 0.f);
    const float4* sv = (const float4*)(s_in + vs * 192);   // 48 float4
    int vbase = vs * 192;
    #pragma unroll 4
    for (int v4 = 0; v4 < 48; v4++) {
        float4 x = sv[v4];
        float4 w0 = ((const float4*)(Wl1 + (vbase + v4 * 4 + 0) * FF))[fq];
        float4 w1 = ((const float4*)(Wl1 + (vbase + v4 * 4 + 1) * FF))[fq];
        float4 w2 = ((const float4*)(Wl1 + (vbase + v4 * 4 + 2) * FF))[fq];
        float4 w3 = ((const float4*)(Wl1 + (vbase + v4 * 4 + 3) * FF))[fq];
        acc.x = fmaf(x.x, w0.x, acc.x); acc.y = fmaf(x.x, w0.y, acc.y);
        acc.z = fmaf(x.x, w0.z, acc.z); acc.w = fmaf(x.x, w0.w, acc.w);
        acc.x = fmaf(x.y, w1.x, acc.x); acc.y = fmaf(x.y, w1.y, acc.y);
        acc.z = fmaf(x.y, w1.z, acc.z); acc.w = fmaf(x.y, w1.w, acc.w);
        acc.x = fmaf(x.z, w2.x, acc.x); acc.y = fmaf(x.z, w2.y, acc.y);
        acc.z = fmaf(x.z, w2.z, acc.z); acc.w = fmaf(x.z, w2.w, acc.w);
        acc.x = fmaf(x.w, w3.x, acc.x); acc.y = fmaf(x.w, w3.y, acc.y);
        acc.z = fmaf(x.w, w3.z, acc.z); acc.w = fmaf(x.w, w3.w, acc.w);
    }
    s_part[vs][fq] = acc;
    __syncthreads();
    if (tid < 32) {
        float4 a = s_part[0][tid], b = s_part[1][tid];
        float4 c = s_part[2][tid], d = s_part[3][tid];
        float4 bi = ((const float4*)bl1)[tid];
        float4 o;
        o.x = a.x + b.x + c.x + d.x + bi.x;
        o.y = a.y + b.y + c.y + d.y + bi.y;
        o.z = a.z + b.z + c.z + d.z + bi.z;
        o.w = a.w + b.w + c.w + d.w + bi.w;
        ((float4*)(g_hl + r * FF))[tid] = o;
    }
}

// ---------------- kernel 2: BatchNorm (redundant stats) + ReLU + Linear ------
__global__ __launch_bounds__(128) void k_langBC(
    const float* __restrict__ bng, const float* __restrict__ bnb,
    const float* __restrict__ Wl2, const float* __restrict__ bl2)
{
    int r = blockIdx.x, f = threadIdx.x;
    __shared__ __align__(16) float s_h[FF];
    __shared__ __align__(16) float4 s_part[4][32];
    const int R = BB * LL;

    float m = 0.f;
    #pragma unroll 8
    for (int rr = 0; rr < R; rr++) m += g_hl[rr * FF + f];
    m *= (1.f / R);
    float v = 0.f;
    #pragma unroll 8
    for (int rr = 0; rr < R; rr++) { float d = g_hl[rr * FF + f] - m; v = fmaf(d, d, v); }
    v *= (1.f / R);
    float h = (g_hl[r * FF + f] - m) * rsqrtf(v + 1e-5f) * bng[f] + bnb[f];
    s_h[f] = fmaxf(h, 0.f);
    __syncthreads();

    int fq = f & 31, vs = f >> 5;
    float4 acc = make_float4(0.f, 0.f, 0.f, 0.f);
    #pragma unroll 8
    for (int c = vs * 32; c < vs * 32 + 32; c++) {
        float x = s_h[c];
        float4 w = ((const float4*)(Wl2 + c * FF))[fq];
        acc.x = fmaf(x, w.x, acc.x); acc.y = fmaf(x, w.y, acc.y);
        acc.z = fmaf(x, w.z, acc.z); acc.w = fmaf(x, w.w, acc.w);
    }
    s_part[vs][fq] = acc;
    __syncthreads();
    if (f < 32) {
        float4 a = s_part[0][f], b = s_part[1][f];
        float4 c = s_part[2][f], d = s_part[3][f];
        float4 bi = ((const float4*)bl2)[f];
        float4 o;
        o.x = a.x + b.x + c.x + d.x + bi.x;
        o.y = a.y + b.y + c.y + d.y + bi.y;
        o.z = a.z + b.z + c.z + d.z + bi.z;
        o.w = a.w + b.w + c.w + d.w + bi.w;
        ((float4*)(g_lang + r * FF))[f] = o;
    }
}

// ---------------- kernel 3 (FAT): feat_encoder+atten || batched kNN ----------
// blocks [0,512):  8 points each, warp per point, float4 GEMMs, fused atten
// blocks [512,1024): 8 kNN queries each, warp per query, register top-16
__global__ __launch_bounds__(256) void k_main(
    const float* __restrict__ xyz, const float* __restrict__ X,
    const float* __restrict__ W1, const float* __restrict__ b1,
    const float* __restrict__ lng, const float* __restrict__ lnb,
    const float* __restrict__ W2, const float* __restrict__ b2)
{
    __shared__ __align__(16) float s_buf[3072];  // 12KB, aliased per branch
    int tid = threadIdx.x, lane = tid & 31, warp = tid >> 5;

    if (blockIdx.x < 512) {
        // ================= feat encoder + attention logits =================
        int p0 = blockIdx.x * 8;
        float* s_in = s_buf;          // [8][256]
        float* s_h  = s_buf + 2048;   // [8][128]
        for (int t = tid; t < 8 * FV; t += 256)
            s_in[t] = X[p0 * FV + t];
        __syncthreads();

        int p = p0 + warp;
        const float4* sv = (const float4*)(s_in + warp * FV);  // 64 float4
        float4 acc = ((const float4*)b1)[lane];
        #pragma unroll 4
        for (int v4 = 0; v4 < 64; v4++) {
            float4 x = sv[v4];
            float4 w0 = ((const float4*)(W1 + (v4 * 4 + 0) * FF))[lane];
            float4 w1 = ((const float4*)(W1 + (v4 * 4 + 1) * FF))[lane];
            float4 w2 = ((const float4*)(W1 + (v4 * 4 + 2) * FF))[lane];
            float4 w3 = ((const float4*)(W1 + (v4 * 4 + 3) * FF))[lane];
            acc.x = fmaf(x.x, w0.x, acc.x); acc.y = fmaf(x.x, w0.y, acc.y);
            acc.z = fmaf(x.x, w0.z, acc.z); acc.w = fmaf(x.x, w0.w, acc.w);
            acc.x = fmaf(x.y, w1.x, acc.x); acc.y = fmaf(x.y, w1.y, acc.y);
            acc.z = fmaf(x.y, w1.z, acc.z); acc.w = fmaf(x.y, w1.w, acc.w);
            acc.x = fmaf(x.z, w2.x, acc.x); acc.y = fmaf(x.z, w2.y, acc.y);
            acc.z = fmaf(x.z, w2.z, acc.z); acc.w = fmaf(x.z, w2.w, acc.w);
            acc.x = fmaf(x.w, w3.x, acc.x); acc.y = fmaf(x.w, w3.y, acc.y);
            acc.z = fmaf(x.w, w3.z, acc.z); acc.w = fmaf(x.w, w3.w, acc.w);
        }

        // LayerNorm — pure warp shuffles (warp == one point)
        float s = acc.x + acc.y + acc.z + acc.w;
        #pragma unroll
        for (int o = 16; o; o >>= 1) s += __shfl_xor_sync(0xffffffffu, s, o);
        float mean = s * (1.f / FF);
        float dx = acc.x - mean, dy = acc.y - mean, dz = acc.z - mean, dw = acc.w - mean;
        float q = dx * dx + dy * dy + dz * dz + dw * dw;
        #pragma unroll
        for (int o = 16; o; o >>= 1) q += __shfl_xor_sync(0xffffffffu, q, o);
        float inv = rsqrtf(q * (1.f / FF) + 1e-5f);
        float4 g  = ((const float4*)lng)[lane];
        float4 bb = ((const float4*)lnb)[lane];
        float4 h;
        h.x = fmaxf(fmaf(dx * inv, g.x, bb.x), 0.f);
        h.y = fmaxf(fmaf(dy * inv, g.y, bb.y), 0.f);
        h.z = fmaxf(fmaf(dz * inv, g.z, bb.z), 0.f);
        h.w = fmaxf(fmaf(dw * inv, g.w, bb.w), 0.f);
        ((float4*)(s_h + warp * FF))[lane] = h;
        __syncwarp();

        float4 o2 = ((const float4*)b2)[lane];
        const float4* sh = (const float4*)(s_h + warp * FF);   // 32 float4
        #pragma unroll 4
        for (int c4 = 0; c4 < 32; c4++) {
            float4 x = sh[c4];
            float4 w0 = ((const float4*)(W2 + (c4 * 4 + 0) * FF))[lane];
            float4 w1 = ((const float4*)(W2 + (c4 * 4 + 1) * FF))[lane];
            float4 w2_ = ((const float4*)(W2 + (c4 * 4 + 2) * FF))[lane];
            float4 w3 = ((const float4*)(W2 + (c4 * 4 + 3) * FF))[lane];
            o2.x = fmaf(x.x, w0.x, o2.x); o2.y = fmaf(x.x, w0.y, o2.y);
            o2.z = fmaf(x.x, w0.z, o2.z); o2.w = fmaf(x.x, w0.w, o2.w);
            o2.x = fmaf(x.y, w1.x, o2.x); o2.y = fmaf(x.y, w1.y, o2.y);
            o2.z = fmaf(x.y, w1.z, o2.z); o2.w = fmaf(x.y, w1.w, o2.w);
            o2.x = fmaf(x.z, w2_.x, o2.x); o2.y = fmaf(x.z, w2_.y, o2.y);
            o2.z = fmaf(x.z, w2_.z, o2.z); o2.w = fmaf(x.z, w2_.w, o2.w);
            o2.x = fmaf(x.w, w3.x, o2.x); o2.y = fmaf(x.w, w3.y, o2.y);
            o2.z = fmaf(x.w, w3.z, o2.z); o2.w = fmaf(x.w, w3.w, o2.w);
        }
        ((float4*)(g_feats + p * FF))[lane] = o2;

        // attention logits: 16 warp-dot-products against lang rows
        int b = p >> 10;   // batch (points are batch-contiguous)
        const float* lb = g_lang + b * LL * FF;
        #pragma unroll
        for (int l = 0; l < LL; l++) {
            float4 lw = ((const float4*)(lb + l * FF))[lane];
            float d = o2.x * lw.x + o2.y * lw.y + o2.z * lw.z + o2.w * lw.w;
            #pragma unroll
            for (int o = 16; o; o >>= 1) d += __shfl_xor_sync(0xffffffffu, d, o);
            if (lane == 0) g_atten[p * LL + l] = d;
        }
    } else {
        // ======================= batched kNN ===============================
        int kb = blockIdx.x - 512;        // 0..511
        int bq = kb >> 7;                 // batch (128 blocks per batch)
        int lq = (kb & 127) * 8 + warp;   // local query id
        int q  = bq * NPER + lq;          // global query id

        float* s_x = s_buf;
        float* s_y = s_buf + 1024;
        float* s_z = s_buf + 2048;
        for (int t = tid; t < NPER; t += 256) {
            int g = (bq * NPER + t) * 3;
            s_x[t] = xyz[g]; s_y[t] = xyz[g + 1]; s_z[t] = xyz[g + 2];
        }
        __syncthreads();

        float qx = s_x[lq], qy = s_y[lq], qz = s_z[lq];
        float d[32];
        #pragma unroll
        for (int m = 0; m < 32; m++) {
            int j = m * 32 + lane;        // conflict-free, index-ordered per lane
            float dx = qx - s_x[j], dy = qy - s_y[j], dz = qz - s_z[j];
            d[m] = dx * dx + dy * dy + dz * dz;
        }

        unsigned sel = 0u;
        for (int r = 0; r < KNN; r++) {
            float mv = 3.4e38f; int mm = 0;
            #pragma unroll
            for (int m = 0; m < 32; m++) {
                bool ok = !((sel >> m) & 1u) && (d[m] < mv);
                if (ok) { mv = d[m]; mm = m; }
            }
            int gi = mm * 32 + lane;
            #pragma unroll
            for (int o = 16; o; o >>= 1) {
                float ov = __shfl_xor_sync(0xffffffffu, mv, o);
                int   oi = __shfl_xor_sync(0xffffffffu, gi, o);
                if (ov < mv || (ov == mv && oi < gi)) { mv = ov; gi = oi; }
            }
            if ((gi & 31) == lane) sel |= 1u << (gi >> 5);
            if (lane == 0) g_knn[q * KNN + r] = bq * NPER + gi;
        }
    }
}

// ---------------- kernel 4: edges: softmax + rel MLP + message + sum ---------
__global__ __launch_bounds__(FF) void k_edge(
    const float* __restrict__ xyz, const int* __restrict__ bidx,
    const float* __restrict__ mask,
    const float* __restrict__ Wr1, const float* __restrict__ br1,
    const float* __restrict__ Wr2, const float* __restrict__ br2,
    float* __restrict__ out)
{
    int i = blockIdx.x, f = threadIdx.x;
    __shared__ int   s_nb[KNN];
    __shared__ __align__(16) float s_a[KNN][LL];     // attention weights
    __shared__ __align__(16) float s_hid[KNN][64];   // rel MLP hidden
    __shared__ __align__(16) float s_geo[KNN][10];   // geometric edge features

    if (f < KNN) s_nb[f] = g_knn[i * KNN + f];
    __syncthreads();

    // load neighbor logits: 256 values, 2 per thread
    {
        int j = f >> 4, l = f & 15;
        s_a[j][l] = g_atten[s_nb[j] * LL + l];
        int f2 = f + 128; j = f2 >> 4; l = f2 & 15;
        s_a[j][l] = g_atten[s_nb[j] * LL + l];
    }
    __syncthreads();

    // phase A: per-l softmax over the 16 neighbors, * mask[i,l]
    if (f < LL) {
        int l = f;
        float m = -3.4e38f;
        #pragma unroll
        for (int j = 0; j < KNN; j++) m = fmaxf(m, s_a[j][l]);
        float e[KNN]; float sum = 0.f;
        #pragma unroll
        for (int j = 0; j < KNN; j++) { e[j] = expf(s_a[j][l] - m); sum += e[j]; }
        float scale = mask[i * LL + l] / sum;
        #pragma unroll
        for (int j = 0; j < KNN; j++) s_a[j][l] = e[j] * scale;
    }
    __syncthreads();

    // phase B: per-edge renormalization over l + geometric features
    if (f < KNN) {
        int j = f;
        float s = 0.f;
        #pragma unroll
        for (int l = 0; l < LL; l++) s += s_a[j][l];
        float inv = 1.f / (s + 1e-7f);
        #pragma unroll
        for (int l = 0; l < LL; l++) s_a[j][l] *= inv;

        int nj = s_nb[j];
        float xi0 = xyz[i * 3], xi1 = xyz[i * 3 + 1], xi2 = xyz[i * 3 + 2];
        float xj0 = xyz[nj * 3], xj1 = xyz[nj * 3 + 1], xj2 = xyz[nj * 3 + 2];
        float d0 = xi0 - xj0, d1 = xi1 - xj1, d2 = xi2 - xj2;
        float nr = sqrtf(d0 * d0 + d1 * d1 + d2 * d2 + 1e-12f);
        s_geo[j][0] = xi0; s_geo[j][1] = xi1; s_geo[j][2] = xi2;
        s_geo[j][3] = xj0; s_geo[j][4] = xj1; s_geo[j][5] = xj2;
        s_geo[j][6] = d0;  s_geo[j][7] = d1;  s_geo[j][8] = d2;
        s_geo[j][9] = nr;
    }
    __syncthreads();

    // rel MLP hidden layer: 128 threads = 2 neighbors x 64 hidden units
    {
        int h = f & 63, jh = f >> 6;
        #pragma unroll
        for (int it = 0; it < 8; it++) {
            int j = it * 2 + jh;
            float acc = br1[h];
            #pragma unroll
            for (int dd = 0; dd < 10; dd++) acc = fmaf(s_geo[j][dd], Wr1[dd * 64 + h], acc);
            s_hid[j][h] = fmaxf(acc, 0.f);
        }
    }
    __syncthreads();

    // rel MLP output: hoist Wr2 over neighbors; float2-pack hidden reads
    float ew[KNN];
    float brf = br2[f];
    #pragma unroll
    for (int j = 0; j < KNN; j++) ew[j] = brf;
    for (int h = 0; h < 64; h += 2) {
        float w0 = Wr2[h * FF + f];
        float w1 = Wr2[(h + 1) * FF + f];
        #pragma unroll
        for (int j = 0; j < KNN; j++) {
            float2 hv = *(const float2*)&s_hid[j][h];
            ew[j] = fmaf(hv.x, w0, ew[j]);
            ew[j] = fmaf(hv.y, w1, ew[j]);
        }
    }

    // ctx = att @ lang_b : hoist lang over neighbors; float2-pack att reads
    float ctx[KNN];
    #pragma unroll
    for (int j = 0; j < KNN; j++) ctx[j] = 0.f;
    int b = bidx[i];
    const float* lb = g_lang + b * LL * FF;
    #pragma unroll
    for (int l = 0; l < LL; l += 2) {
        float w0 = lb[l * FF + f];
        float w1 = lb[(l + 1) * FF + f];
        #pragma unroll
        for (int j = 0; j < KNN; j++) {
            float2 av = *(const float2*)&s_a[j][l];
            ctx[j] = fmaf(av.x, w0, ctx[j]);
            ctx[j] = fmaf(av.y, w1, ctx[j]);
        }
    }

    // msg = feats[col] * ctx * ew ; sum over neighbors ; residual add
    float o = g_feats[i * FF + f];
    #pragma unroll
    for (int j = 0; j < KNN; j++)
        o += g_feats[s_nb[j] * FF + f] * ctx[j] * ew[j];
    out[i * FF + f] = o;
}

// ---------------- launch ------------------------------------------------------
extern "C" void kernel_launch(void* const* d_in, const int* in_sizes, int n_in,
                              void* d_out, int out_size)
{
    const float* xyz   = (const float*)d_in[0];
    const int*   bidx  = (const int*)  d_in[1];
    const float* feats = (const float*)d_in[2];
    const float* lft   = (const float*)d_in[3];
    const float* mask  = (const float*)d_in[4];
    const float* W1    = (const float*)d_in[5];
    const float* b1    = (const float*)d_in[6];
    const float* lng   = (const float*)d_in[7];
    const float* lnb   = (const float*)d_in[8];
    const float* W2    = (const float*)d_in[9];
    const float* b2    = (const float*)d_in[10];
    const float* Wl1   = (const float*)d_in[11];
    const float* bl1   = (const float*)d_in[12];
    const float* bng   = (const float*)d_in[13];
    const float* bnb   = (const float*)d_in[14];
    const float* Wl2   = (const float*)d_in[15];
    const float* bl2   = (const float*)d_in[16];
    const float* Wr1   = (const float*)d_in[17];
    const float* br1   = (const float*)d_in[18];
    const float* Wr2   = (const float*)d_in[19];
    const float* br2   = (const float*)d_in[20];
    float* out = (float*)d_out;

    k_langA<<<BB * LL, 128>>>(lft, Wl1, bl1);
    k_langBC<<<BB * LL, 128>>>(bng, bnb, Wl2, bl2);
    k_main<<<1024, 256>>>(xyz, feats, W1, b1, lng, lnb, W2, b2);
    k_edge<<<NPTS, FF>>>(xyz, bidx, mask, Wr1, br1, Wr2, br2, out);
}

// round 9
// speedup vs baseline: 2.7879x; 1.1310x over previous
#include <cuda_runtime.h>
#include <math.h>

// Problem constants (fixed by setup_inputs)
#define NPTS  4096
#define BB    4
#define NPER  1024
#define LL    16
#define FV    256
#define FLANG 768
#define FF    128
#define KNN   16

// ---------------- scratch (device globals; no allocations allowed) -----------
__device__ __align__(16) float g_feats[NPTS * FF];   // encoded point features
__device__ __align__(16) float g_hl[BB * LL * FF];   // lang hidden pre-BN
__device__ __align__(16) float g_lang[BB * LL * FF]; // encoded lang features
__device__ __align__(16) float g_atten[NPTS * LL];   // per-point/token logits
__device__ int   g_knn[NPTS * KNN];                  // neighbor ids (global)

// ---------------- packed f32x2 helpers (sm_103a FFMA2 pipe) ------------------
typedef unsigned long long ull;
__device__ __forceinline__ ull pk2(float x, float y) {
    ull r; asm("mov.b64 %0, {%1, %2};" : "=l"(r) : "f"(x), "f"(y)); return r;
}
__device__ __forceinline__ ull fma2(ull a, ull b, ull c) {
    ull d; asm("fma.rn.f32x2 %0, %1, %2, %3;" : "=l"(d) : "l"(a), "l"(b), "l"(c));
    return d;
}
__device__ __forceinline__ float2 upk(ull a) {
    float2 f; asm("mov.b64 {%0, %1}, %2;" : "=f"(f.x), "=f"(f.y) : "l"(a)); return f;
}

// ---------------- kernel 1: lang first linear (vectorized, v-split) ----------
__global__ __launch_bounds__(128) void k_langA(
    const float* __restrict__ LFT, const float* __restrict__ Wl1,
    const float* __restrict__ bl1)
{
    int r = blockIdx.x, tid = threadIdx.x;
    __shared__ __align__(16) float s_in[FLANG];
    __shared__ __align__(16) float4 s_part[4][32];

    for (int t = tid; t < FLANG; t += 128) s_in[t] = LFT[r * FLANG + t];
    __syncthreads();

    int fq = tid & 31, vs = tid >> 5;
    float4 acc = make_float4(0.f, 0.f, 0.f, 0.f);
    const float4* sv = (const float4*)(s_in + vs * 192);
    int vbase = vs * 192;
    #pragma unroll 4
    for (int v4 = 0; v4 < 48; v4++) {
        float4 x = sv[v4];
        float4 w0 = ((const float4*)(Wl1 + (vbase + v4 * 4 + 0) * FF))[fq];
        float4 w1 = ((const float4*)(Wl1 + (vbase + v4 * 4 + 1) * FF))[fq];
        float4 w2 = ((const float4*)(Wl1 + (vbase + v4 * 4 + 2) * FF))[fq];
        float4 w3 = ((const float4*)(Wl1 + (vbase + v4 * 4 + 3) * FF))[fq];
        acc.x = fmaf(x.x, w0.x, acc.x); acc.y = fmaf(x.x, w0.y, acc.y);
        acc.z = fmaf(x.x, w0.z, acc.z); acc.w = fmaf(x.x, w0.w, acc.w);
        acc.x = fmaf(x.y, w1.x, acc.x); acc.y = fmaf(x.y, w1.y, acc.y);
        acc.z = fmaf(x.y, w1.z, acc.z); acc.w = fmaf(x.y, w1.w, acc.w);
        acc.x = fmaf(x.z, w2.x, acc.x); acc.y = fmaf(x.z, w2.y, acc.y);
        acc.z = fmaf(x.z, w2.z, acc.z); acc.w = fmaf(x.z, w2.w, acc.w);
        acc.x = fmaf(x.w, w3.x, acc.x); acc.y = fmaf(x.w, w3.y, acc.y);
        acc.z = fmaf(x.w, w3.z, acc.z); acc.w = fmaf(x.w, w3.w, acc.w);
    }
    s_part[vs][fq] = acc;
    __syncthreads();
    if (tid < 32) {
        float4 a = s_part[0][tid], b = s_part[1][tid];
        float4 c = s_part[2][tid], d = s_part[3][tid];
        float4 bi = ((const float4*)bl1)[tid];
        float4 o;
        o.x = a.x + b.x + c.x + d.x + bi.x;
        o.y = a.y + b.y + c.y + d.y + bi.y;
        o.z = a.z + b.z + c.z + d.z + bi.z;
        o.w = a.w + b.w + c.w + d.w + bi.w;
        ((float4*)(g_hl + r * FF))[tid] = o;
    }
}

// ---------------- kernel 2: BatchNorm (redundant stats) + ReLU + Linear ------
__global__ __launch_bounds__(128) void k_langBC(
    const float* __restrict__ bng, const float* __restrict__ bnb,
    const float* __restrict__ Wl2, const float* __restrict__ bl2)
{
    int r = blockIdx.x, f = threadIdx.x;
    __shared__ __align__(16) float s_h[FF];
    __shared__ __align__(16) float4 s_part[4][32];
    const int R = BB * LL;

    float m = 0.f;
    #pragma unroll 8
    for (int rr = 0; rr < R; rr++) m += g_hl[rr * FF + f];
    m *= (1.f / R);
    float v = 0.f;
    #pragma unroll 8
    for (int rr = 0; rr < R; rr++) { float d = g_hl[rr * FF + f] - m; v = fmaf(d, d, v); }
    v *= (1.f / R);
    float h = (g_hl[r * FF + f] - m) * rsqrtf(v + 1e-5f) * bng[f] + bnb[f];
    s_h[f] = fmaxf(h, 0.f);
    __syncthreads();

    int fq = f & 31, vs = f >> 5;
    float4 acc = make_float4(0.f, 0.f, 0.f, 0.f);
    #pragma unroll 8
    for (int c = vs * 32; c < vs * 32 + 32; c++) {
        float x = s_h[c];
        float4 w = ((const float4*)(Wl2 + c * FF))[fq];
        acc.x = fmaf(x, w.x, acc.x); acc.y = fmaf(x, w.y, acc.y);
        acc.z = fmaf(x, w.z, acc.z); acc.w = fmaf(x, w.w, acc.w);
    }
    s_part[vs][fq] = acc;
    __syncthreads();
    if (f < 32) {
        float4 a = s_part[0][f], b = s_part[1][f];
        float4 c = s_part[2][f], d = s_part[3][f];
        float4 bi = ((const float4*)bl2)[f];
        float4 o;
        o.x = a.x + b.x + c.x + d.x + bi.x;
        o.y = a.y + b.y + c.y + d.y + bi.y;
        o.z = a.z + b.z + c.z + d.z + bi.z;
        o.w = a.w + b.w + c.w + d.w + bi.w;
        ((float4*)(g_lang + r * FF))[f] = o;
    }
}

// ---------------- kernel 3 (FAT): tiled feat GEMM+LN+GEMM+atten || kNN -------
// blocks [0,128): 32 points each, block-tiled GEMMs with smem-staged weights
// blocks [128,640): 8 kNN queries each, warp per query, register top-16
#define OFF_XT 0        // [32][36]  (stage A, X^T chunk)
#define OFF_W  1152     // [32][128] (stage A/C, W chunk)
#define OFF_HT 5248     // [128][36] (stage B/C, H^T)
#define OFF_O  0        // [32][132] (stage D, O)           -- overlays XT+W
#define OFF_LG 5248     // [16][128] (stage D, lang tile)   -- overlays HT
#define SBUF   9856

__global__ __launch_bounds__(256) void k_fat(
    const float* __restrict__ xyz, const float* __restrict__ X,
    const float* __restrict__ W1, const float* __restrict__ b1,
    const float* __restrict__ lng, const float* __restrict__ lnb,
    const float* __restrict__ W2, const float* __restrict__ b2)
{
    __shared__ __align__(16) float s[SBUF];
    int tid = threadIdx.x, lane = tid & 31, warp = tid >> 5;

    if (blockIdx.x < 128) {
        // ================= tiled feat encoder + attention ==================
        int p0 = blockIdx.x * 32;
        int pg = tid & 7, fg = tid >> 3;   // 8 point-groups x 32 f-groups

        // ---- GEMM1: H = X @ W1 + b1 (packed f32x2 accumulators) ----
        float4 bv = ((const float4*)b1)[fg];
        ull accL[4], accH[4];
        #pragma unroll
        for (int i = 0; i < 4; i++) { accL[i] = pk2(bv.x, bv.y); accH[i] = pk2(bv.z, bv.w); }

        for (int kc = 0; kc < 8; kc++) {
            int k0 = kc * 32;
            {   // stage X chunk transposed: sXT[k][p]
                int p = tid >> 3, kq = (tid & 7) * 4;
                float4 xv = *(const float4*)&X[(p0 + p) * FV + k0 + kq];
                s[OFF_XT + (kq + 0) * 36 + p] = xv.x;
                s[OFF_XT + (kq + 1) * 36 + p] = xv.y;
                s[OFF_XT + (kq + 2) * 36 + p] = xv.z;
                s[OFF_XT + (kq + 3) * 36 + p] = xv.w;
            }
            {   // stage W1 chunk: sW[k][f]
                const float4* wg = (const float4*)(W1 + k0 * FF);
                float4* ws = (float4*)(s + OFF_W);
                #pragma unroll
                for (int r = 0; r < 4; r++) ws[r * 256 + tid] = wg[r * 256 + tid];
            }
            __syncthreads();
            #pragma unroll 8
            for (int kk = 0; kk < 32; kk++) {
                float4 xv = *(const float4*)&s[OFF_XT + kk * 36 + pg * 4];
                ulonglong2 wv = *(const ulonglong2*)&s[OFF_W + kk * FF + fg * 4];
                ull a0 = pk2(xv.x, xv.x), a1 = pk2(xv.y, xv.y);
                ull a2 = pk2(xv.z, xv.z), a3 = pk2(xv.w, xv.w);
                accL[0] = fma2(a0, wv.x, accL[0]); accH[0] = fma2(a0, wv.y, accH[0]);
                accL[1] = fma2(a1, wv.x, accL[1]); accH[1] = fma2(a1, wv.y, accH[1]);
                accL[2] = fma2(a2, wv.x, accL[2]); accH[2] = fma2(a2, wv.y, accH[2]);
                accL[3] = fma2(a3, wv.x, accL[3]); accH[3] = fma2(a3, wv.y, accH[3]);
            }
            __syncthreads();
        }
        // write H^T: sHT[f][p]
        #pragma unroll
        for (int i = 0; i < 4; i++) {
            float2 lo = upk(accL[i]), hi = upk(accH[i]);
            int p = pg * 4 + i;
            s[OFF_HT + (fg * 4 + 0) * 36 + p] = lo.x;
            s[OFF_HT + (fg * 4 + 1) * 36 + p] = lo.y;
            s[OFF_HT + (fg * 4 + 2) * 36 + p] = hi.x;
            s[OFF_HT + (fg * 4 + 3) * 36 + p] = hi.y;
        }
        __syncthreads();

        // ---- LayerNorm + ReLU, in place on sHT (warp handles 4 points) ----
        {
            float g0 = lng[lane], g1 = lng[lane + 32], g2 = lng[lane + 64], g3 = lng[lane + 96];
            float c0 = lnb[lane], c1 = lnb[lane + 32], c2 = lnb[lane + 64], c3 = lnb[lane + 96];
            #pragma unroll
            for (int pp = 0; pp < 4; pp++) {
                int p = warp * 4 + pp;
                float v0 = s[OFF_HT + lane * 36 + p];
                float v1 = s[OFF_HT + (lane + 32) * 36 + p];
                float v2 = s[OFF_HT + (lane + 64) * 36 + p];
                float v3 = s[OFF_HT + (lane + 96) * 36 + p];
                float sm = v0 + v1 + v2 + v3;
                #pragma unroll
                for (int o = 16; o; o >>= 1) sm += __shfl_xor_sync(~0u, sm, o);
                float mean = sm * (1.f / FF);
                float d0 = v0 - mean, d1 = v1 - mean, d2 = v2 - mean, d3 = v3 - mean;
                float q = d0 * d0 + d1 * d1 + d2 * d2 + d3 * d3;
                #pragma unroll
                for (int o = 16; o; o >>= 1) q += __shfl_xor_sync(~0u, q, o);
                float inv = rsqrtf(q * (1.f / FF) + 1e-5f);
                s[OFF_HT + lane * 36 + p]        = fmaxf(fmaf(d0 * inv, g0, c0), 0.f);
                s[OFF_HT + (lane + 32) * 36 + p] = fmaxf(fmaf(d1 * inv, g1, c1), 0.f);
                s[OFF_HT + (lane + 64) * 36 + p] = fmaxf(fmaf(d2 * inv, g2, c2), 0.f);
                s[OFF_HT + (lane + 96) * 36 + p] = fmaxf(fmaf(d3 * inv, g3, c3), 0.f);
            }
        }

        // ---- GEMM2: O = relu(H) @ W2 + b2 ----
        float4 b2v = ((const float4*)b2)[fg];
        ull oL[4], oH[4];
        #pragma unroll
        for (int i = 0; i < 4; i++) { oL[i] = pk2(b2v.x, b2v.y); oH[i] = pk2(b2v.z, b2v.w); }
        for (int kc = 0; kc < 4; kc++) {
            int k0 = kc * 32;
            {   // stage W2 chunk
                const float4* wg = (const float4*)(W2 + k0 * FF);
                float4* ws = (float4*)(s + OFF_W);
                #pragma unroll
                for (int r = 0; r < 4; r++) ws[r * 256 + tid] = wg[r * 256 + tid];
            }
            __syncthreads();
            #pragma unroll 8
            for (int kk = 0; kk < 32; kk++) {
                float4 xv = *(const float4*)&s[OFF_HT + (k0 + kk) * 36 + pg * 4];
                ulonglong2 wv = *(const ulonglong2*)&s[OFF_W + kk * FF + fg * 4];
                ull a0 = pk2(xv.x, xv.x), a1 = pk2(xv.y, xv.y);
                ull a2 = pk2(xv.z, xv.z), a3 = pk2(xv.w, xv.w);
                oL[0] = fma2(a0, wv.x, oL[0]); oH[0] = fma2(a0, wv.y, oH[0]);
                oL[1] = fma2(a1, wv.x, oL[1]); oH[1] = fma2(a1, wv.y, oH[1]);
                oL[2] = fma2(a2, wv.x, oL[2]); oH[2] = fma2(a2, wv.y, oH[2]);
                oL[3] = fma2(a3, wv.x, oL[3]); oH[3] = fma2(a3, wv.y, oH[3]);
            }
            __syncthreads();
        }

        // ---- epilogue: store g_feats, stage O + lang, attention logits ----
        int b = p0 >> 10;
        #pragma unroll
        for (int i = 0; i < 4; i++) {
            float2 lo = upk(oL[i]), hi = upk(oH[i]);
            float4 ov = make_float4(lo.x, lo.y, hi.x, hi.y);
            int p = pg * 4 + i;
            ((float4*)&g_feats[(p0 + p) * FF])[fg] = ov;
            *(float4*)&s[OFF_O + p * 132 + fg * 4] = ov;
        }
        {   // stage lang[b]: 2048 floats
            const float4* lg = (const float4*)(g_lang + b * LL * FF);
            float4* ls = (float4*)(s + OFF_LG);
            ls[tid] = lg[tid];
            ls[tid + 256] = lg[tid + 256];
        }
        __syncthreads();
        #pragma unroll
        for (int pp = 0; pp < 4; pp++) {
            int p = warp * 4 + pp;
            float4 ov = *(const float4*)&s[OFF_O + p * 132 + lane * 4];
            #pragma unroll
            for (int l = 0; l < LL; l++) {
                float4 lv = *(const float4*)&s[OFF_LG + l * FF + lane * 4];
                float d = ov.x * lv.x + ov.y * lv.y + ov.z * lv.z + ov.w * lv.w;
                #pragma unroll
                for (int o = 16; o; o >>= 1) d += __shfl_xor_sync(~0u, d, o);
                if (lane == 0) g_atten[(p0 + p) * LL + l] = d;
            }
        }
    } else {
        // ======================= batched kNN ===============================
        int kb = blockIdx.x - 128;        // 0..511
        int bq = kb >> 7;                 // batch (128 blocks per batch)
        int lq = (kb & 127) * 8 + warp;   // local query id
        int q  = bq * NPER + lq;          // global query id

        float* s_x = s;
        float* s_y = s + 1024;
        float* s_z = s + 2048;
        for (int t = tid; t < NPER; t += 256) {
            int g = (bq * NPER + t) * 3;
            s_x[t] = xyz[g]; s_y[t] = xyz[g + 1]; s_z[t] = xyz[g + 2];
        }
        __syncthreads();

        float qx = s_x[lq], qy = s_y[lq], qz = s_z[lq];
        float d[32];
        #pragma unroll
        for (int m = 0; m < 32; m++) {
            int j = m * 32 + lane;        // conflict-free, index-ordered per lane
            float dx = qx - s_x[j], dy = qy - s_y[j], dz = qz - s_z[j];
            d[m] = dx * dx + dy * dy + dz * dz;
        }

        unsigned sel = 0u;
        for (int r = 0; r < KNN; r++) {
            float mv = 3.4e38f; int mm = 0;
            #pragma unroll
            for (int m = 0; m < 32; m++) {
                bool ok = !((sel >> m) & 1u) && (d[m] < mv);
                if (ok) { mv = d[m]; mm = m; }
            }
            int gi = mm * 32 + lane;
            #pragma unroll
            for (int o = 16; o; o >>= 1) {
                float ov = __shfl_xor_sync(0xffffffffu, mv, o);
                int   oi = __shfl_xor_sync(0xffffffffu, gi, o);
                if (ov < mv || (ov == mv && oi < gi)) { mv = ov; gi = oi; }
            }
            if ((gi & 31) == lane) sel |= 1u << (gi >> 5);
            if (lane == 0) g_knn[q * KNN + r] = bq * NPER + gi;
        }
    }
}

// ---------------- kernel 4: edges, register-micro-tiled (4j x 4f / thread) ---
__global__ __launch_bounds__(FF) void k_edge(
    const float* __restrict__ xyz,
    const float* __restrict__ mask,
    const float* __restrict__ Wr1, const float* __restrict__ br1,
    const float* __restrict__ Wr2, const float* __restrict__ br2,
    float* __restrict__ out)
{
    int i = blockIdx.x, tid = threadIdx.x;
    __shared__ int s_nb[KNN];
    __shared__ __align__(16) float s_aT[LL][16];     // [l][j] attention
    __shared__ __align__(16) float s_hidT[64][20];   // [h][j] rel hidden (pad 20)
    __shared__ float s_geo[KNN][10];

    if (tid < KNN) s_nb[tid] = g_knn[i * KNN + tid];
    __syncthreads();

    {   // load neighbor logits transposed: 256 values, 2 per thread
        int j = tid >> 4, l = tid & 15;
        s_aT[l][j]     = g_atten[s_nb[j] * LL + l];
        s_aT[l][j + 8] = g_atten[s_nb[j + 8] * LL + l];
    }
    __syncthreads();

    // phase A: per-l softmax over the 16 neighbors, * mask[i,l]
    if (tid < LL) {
        int l = tid;
        float m = -3.4e38f;
        #pragma unroll
        for (int j = 0; j < KNN; j++) m = fmaxf(m, s_aT[l][j]);
        float e[KNN]; float sum = 0.f;
        #pragma unroll
        for (int j = 0; j < KNN; j++) { e[j] = expf(s_aT[l][j] - m); sum += e[j]; }
        float scale = mask[i * LL + l] / sum;
        #pragma unroll
        for (int j = 0; j < KNN; j++) s_aT[l][j] = e[j] * scale;
    }
    __syncthreads();

    // phase B: per-edge renormalization over l + geometric features
    if (tid < KNN) {
        int j = tid;
        float ssum = 0.f;
        #pragma unroll
        for (int l = 0; l < LL; l++) ssum += s_aT[l][j];
        float inv = 1.f / (ssum + 1e-7f);
        #pragma unroll
        for (int l = 0; l < LL; l++) s_aT[l][j] *= inv;

        int nj = s_nb[j];
        float xi0 = xyz[i * 3], xi1 = xyz[i * 3 + 1], xi2 = xyz[i * 3 + 2];
        float xj0 = xyz[nj * 3], xj1 = xyz[nj * 3 + 1], xj2 = xyz[nj * 3 + 2];
        float d0 = xi0 - xj0, d1 = xi1 - xj1, d2 = xi2 - xj2;
        float nr = sqrtf(d0 * d0 + d1 * d1 + d2 * d2 + 1e-12f);
        s_geo[j][0] = xi0; s_geo[j][1] = xi1; s_geo[j][2] = xi2;
        s_geo[j][3] = xj0; s_geo[j][4] = xj1; s_geo[j][5] = xj2;
        s_geo[j][6] = d0;  s_geo[j][7] = d1;  s_geo[j][8] = d2;
        s_geo[j][9] = nr;
    }
    __syncthreads();

    // rel MLP hidden, stored transposed: thread (h=tid>>1, jh=tid&1), 8 j each
    {
        int h = tid >> 1, jh = tid & 1;
        float w[10];
        #pragma unroll
        for (int dd = 0; dd < 10; dd++) w[dd] = Wr1[dd * 64 + h];
        float bb = br1[h];
        #pragma unroll
        for (int jj = 0; jj < 8; jj++) {
            int j = jj * 2 + jh;
            float a = bb;
            #pragma unroll
            for (int dd = 0; dd < 10; dd++) a = fmaf(s_geo[j][dd], w[dd], a);
            s_hidT[h][j] = fmaxf(a, 0.f);
        }
    }
    __syncthreads();

    int jg = tid & 3, fg = tid >> 2;    // 4 j-groups x 32 f-groups

    // ew[4j][4f] = hid @ Wr2 + br2  (packed f32x2)
    float4 b2v = ((const float4*)br2)[fg];
    ull ewL[4], ewH[4];
    #pragma unroll
    for (int jj = 0; jj < 4; jj++) { ewL[jj] = pk2(b2v.x, b2v.y); ewH[jj] = pk2(b2v.z, b2v.w); }
    #pragma unroll 8
    for (int k = 0; k < 64; k++) {
        float4 hv = *(const float4*)&s_hidT[k][jg * 4];
        ulonglong2 wv = *(const ulonglong2*)&Wr2[k * FF + fg * 4];
        ull a0 = pk2(hv.x, hv.x), a1 = pk2(hv.y, hv.y);
        ull a2 = pk2(hv.z, hv.z), a3 = pk2(hv.w, hv.w);
        ewL[0] = fma2(a0, wv.x, ewL[0]); ewH[0] = fma2(a0, wv.y, ewH[0]);
        ewL[1] = fma2(a1, wv.x, ewL[1]); ewH[1] = fma2(a1, wv.y, ewH[1]);
        ewL[2] = fma2(a2, wv.x, ewL[2]); ewH[2] = fma2(a2, wv.y, ewH[2]);
        ewL[3] = fma2(a3, wv.x, ewL[3]); ewH[3] = fma2(a3, wv.y, ewH[3]);
    }

    // ctx[4j][4f] = att @ lang_b  (packed f32x2)
    ull cxL[4] = {0ull, 0ull, 0ull, 0ull}, cxH[4] = {0ull, 0ull, 0ull, 0ull};
    const float* lb = g_lang + (i >> 10) * LL * FF;
    #pragma unroll
    for (int l = 0; l < LL; l++) {
        float4 av = *(const float4*)&s_aT[l][jg * 4];
        ulonglong2 lv = *(const ulonglong2*)&lb[l * FF + fg * 4];
        ull a0 = pk2(av.x, av.x), a1 = pk2(av.y, av.y);
        ull a2 = pk2(av.z, av.z), a3 = pk2(av.w, av.w);
        cxL[0] = fma2(a0, lv.x, cxL[0]); cxH[0] = fma2(a0, lv.y, cxH[0]);
        cxL[1] = fma2(a1, lv.x, cxL[1]); cxH[1] = fma2(a1, lv.y, cxH[1]);
        cxL[2] = fma2(a2, lv.x, cxL[2]); cxH[2] = fma2(a2, lv.y, cxH[2]);
        cxL[3] = fma2(a3, lv.x, cxL[3]); cxH[3] = fma2(a3, lv.y, cxH[3]);
    }

    // msg = feats[col] * ctx * ew, partial-sum over this thread's 4 j
    float4 res = make_float4(0.f, 0.f, 0.f, 0.f);
    #pragma unroll
    for (int jj = 0; jj < 4; jj++) {
        int nj = s_nb[jg * 4 + jj];
        float4 fv = ((const float4*)&g_feats[nj * FF])[fg];
        float2 eL = upk(ewL[jj]), eH = upk(ewH[jj]);
        float2 cL = upk(cxL[jj]), cH = upk(cxH[jj]);
        res.x = fmaf(fv.x * cL.x, eL.x, res.x);
        res.y = fmaf(fv.y * cL.y, eL.y, res.y);
        res.z = fmaf(fv.z * cH.x, eH.x, res.z);
        res.w = fmaf(fv.w * cH.y, eH.y, res.w);
    }
    // reduce the 4 jg-threads sharing this f-quad (xor 1, 2 within 4-group)
    #pragma unroll
    for (int o = 1; o <= 2; o <<= 1) {
        res.x += __shfl_xor_sync(~0u, res.x, o);
        res.y += __shfl_xor_sync(~0u, res.y, o);
        res.z += __shfl_xor_sync(~0u, res.z, o);
        res.w += __shfl_xor_sync(~0u, res.w, o);
    }
    if (jg == 0) {
        float4 rv = ((const float4*)&g_feats[i * FF])[fg];
        res.x += rv.x; res.y += rv.y; res.z += rv.z; res.w += rv.w;
        ((float4*)&out[i * FF])[fg] = res;
    }
}

// ---------------- launch ------------------------------------------------------
extern "C" void kernel_launch(void* const* d_in, const int* in_sizes, int n_in,
                              void* d_out, int out_size)
{
    const float* xyz   = (const float*)d_in[0];
    const float* feats = (const float*)d_in[2];
    const float* lft   = (const float*)d_in[3];
    const float* mask  = (const float*)d_in[4];
    const float* W1    = (const float*)d_in[5];
    const float* b1    = (const float*)d_in[6];
    const float* lng   = (const float*)d_in[7];
    const float* lnb   = (const float*)d_in[8];
    const float* W2    = (const float*)d_in[9];
    const float* b2    = (const float*)d_in[10];
    const float* Wl1   = (const float*)d_in[11];
    const float* bl1   = (const float*)d_in[12];
    const float* bng   = (const float*)d_in[13];
    const float* bnb   = (const float*)d_in[14];
    const float* Wl2   = (const float*)d_in[15];
    const float* bl2   = (const float*)d_in[16];
    const float* Wr1   = (const float*)d_in[17];
    const float* br1   = (const float*)d_in[18];
    const float* Wr2   = (const float*)d_in[19];
    const float* br2   = (const float*)d_in[20];
    float* out = (float*)d_out;

    k_langA<<<BB * LL, 128>>>(lft, Wl1, bl1);
    k_langBC<<<BB * LL, 128>>>(bng, bnb, Wl2, bl2);
    k_fat<<<640, 256>>>(xyz, feats, W1, b1, lng, lnb, W2, b2);
    k_edge<<<NPTS, FF>>>(xyz, mask, Wr1, br1, Wr2, br2, out);
}

// round 10
// speedup vs baseline: 2.9790x; 1.0685x over previous
#include <cuda_runtime.h>
#include <math.h>

// Problem constants (fixed by setup_inputs)
#define NPTS  4096
#define BB    4
#define NPER  1024
#define LL    16
#define FV    256
#define FLANG 768
#define FF    128
#define KNN   16

// ---------------- scratch (device globals; no allocations allowed) -----------
__device__ __align__(16) float g_feats[NPTS * FF];   // encoded point features
__device__ __align__(16) float g_hl[BB * LL * FF];   // lang hidden pre-BN
__device__ __align__(16) float g_lang[BB * LL * FF]; // encoded lang features
__device__ __align__(16) float g_atten[NPTS * LL];   // per-point/token logits
__device__ int   g_knn[NPTS * KNN];                  // neighbor ids (global)
__device__ int   g_c1, g_c2;                         // inter-block barrier counters

// ---------------- packed f32x2 helpers (sm_103a FFMA2 pipe) ------------------
typedef unsigned long long ull;
__device__ __forceinline__ ull pk2(float x, float y) {
    ull r; asm("mov.b64 %0, {%1, %2};" : "=l"(r) : "f"(x), "f"(y)); return r;
}
__device__ __forceinline__ ull fma2(ull a, ull b, ull c) {
    ull d; asm("fma.rn.f32x2 %0, %1, %2, %3;" : "=l"(d) : "l"(a), "l"(b), "l"(c));
    return d;
}
__device__ __forceinline__ float2 upk(ull a) {
    float2 f; asm("mov.b64 {%0, %1}, %2;" : "=f"(f.x), "=f"(f.y) : "l"(a)); return f;
}

// ---------------- kernel 0: reset barrier counters ---------------------------
__global__ void k_reset() {
    if (threadIdx.x == 0) { g_c1 = 0; g_c2 = 0; }
}

// ---------------- MEGA kernel: lang | feat+atten | kNN -----------------------
// bids [0,64):    lang pipeline (2 phases, inter-block barrier on g_c1/g_c2)
// bids [64,192):  32 points each, block-tiled feat GEMMs + atten epilogue
// bids [192,704): 8 kNN queries each, warp per query, register top-16
#define OFF_XT 0        // [32][36]  (feat stage A, X^T chunk)
#define OFF_W  1152     // [32][128] (feat stage A/C, W chunk)
#define OFF_HT 5248     // [128][36] (feat stage B/C, H^T)
#define OFF_O  0        // [32][132] (feat stage D, O)         -- overlays XT+W
#define OFF_LG 5248     // [16][128] (feat stage D, lang tile) -- overlays HT
#define SBUF   9856

__global__ __launch_bounds__(256) void k_mega(
    const float* __restrict__ xyz, const float* __restrict__ X,
    const float* __restrict__ W1, const float* __restrict__ b1,
    const float* __restrict__ lng, const float* __restrict__ lnb,
    const float* __restrict__ W2, const float* __restrict__ b2,
    const float* __restrict__ LFT, const float* __restrict__ Wl1,
    const float* __restrict__ bl1, const float* __restrict__ bng,
    const float* __restrict__ bnb, const float* __restrict__ Wl2,
    const float* __restrict__ bl2)
{
    __shared__ __align__(16) float s[SBUF];
    int bid = blockIdx.x, tid = threadIdx.x, lane = tid & 31, warp = tid >> 5;

    if (bid < 64) {
        // ========================= LANG pipeline ===========================
        int r = bid;
        float* s_in = s;                            // 768 floats (also s_h)
        float4* s_part = (float4*)(s + 768);        // [8][32] float4

        // phase 1: hl = LFT @ Wl1 + bl1 (8-way v-split, 256 threads)
        for (int t = tid; t < FLANG; t += 256) s_in[t] = LFT[r * FLANG + t];
        __syncthreads();
        int fq = tid & 31, vs = tid >> 5;
        float4 acc = make_float4(0.f, 0.f, 0.f, 0.f);
        const float4* sv = (const float4*)(s_in + vs * 96);   // 24 float4
        int vbase = vs * 96;
        #pragma unroll 4
        for (int v4 = 0; v4 < 24; v4++) {
            float4 x = sv[v4];
            float4 w0 = ((const float4*)(Wl1 + (vbase + v4 * 4 + 0) * FF))[fq];
            float4 w1 = ((const float4*)(Wl1 + (vbase + v4 * 4 + 1) * FF))[fq];
            float4 w2 = ((const float4*)(Wl1 + (vbase + v4 * 4 + 2) * FF))[fq];
            float4 w3 = ((const float4*)(Wl1 + (vbase + v4 * 4 + 3) * FF))[fq];
            acc.x = fmaf(x.x, w0.x, acc.x); acc.y = fmaf(x.x, w0.y, acc.y);
            acc.z = fmaf(x.x, w0.z, acc.z); acc.w = fmaf(x.x, w0.w, acc.w);
            acc.x = fmaf(x.y, w1.x, acc.x); acc.y = fmaf(x.y, w1.y, acc.y);
            acc.z = fmaf(x.y, w1.z, acc.z); acc.w = fmaf(x.y, w1.w, acc.w);
            acc.x = fmaf(x.z, w2.x, acc.x); acc.y = fmaf(x.z, w2.y, acc.y);
            acc.z = fmaf(x.z, w2.z, acc.z); acc.w = fmaf(x.z, w2.w, acc.w);
            acc.x = fmaf(x.w, w3.x, acc.x); acc.y = fmaf(x.w, w3.y, acc.y);
            acc.z = fmaf(x.w, w3.z, acc.z); acc.w = fmaf(x.w, w3.w, acc.w);
        }
        s_part[vs * 32 + fq] = acc;
        __syncthreads();
        if (tid < 32) {
            float4 o = ((const float4*)bl1)[tid];
            #pragma unroll
            for (int p = 0; p < 8; p++) {
                float4 a = s_part[p * 32 + tid];
                o.x += a.x; o.y += a.y; o.z += a.z; o.w += a.w;
            }
            ((float4*)(g_hl + r * FF))[tid] = o;
            __threadfence();
        }
        __syncthreads();
        if (tid == 0) {
            atomicAdd(&g_c1, 1);
            while (atomicAdd(&g_c1, 0) < 64) __nanosleep(64);
        }
        __syncthreads();
        __threadfence();

        // phase 2: BN (global stats, recomputed redundantly) + ReLU
        if (tid < FF) {
            int f = tid;
            float m = 0.f;
            #pragma unroll 8
            for (int rr = 0; rr < 64; rr++) m += g_hl[rr * FF + f];
            m *= (1.f / 64.f);
            float v = 0.f;
            #pragma unroll 8
            for (int rr = 0; rr < 64; rr++) { float d = g_hl[rr * FF + f] - m; v = fmaf(d, d, v); }
            v *= (1.f / 64.f);
            float h = (g_hl[r * FF + f] - m) * rsqrtf(v + 1e-5f) * bng[f] + bnb[f];
            s_in[f] = fmaxf(h, 0.f);
        }
        __syncthreads();

        // phase 3: lang = relu(h) @ Wl2 + bl2 (8-way c-split)
        float4 acc2 = make_float4(0.f, 0.f, 0.f, 0.f);
        #pragma unroll 8
        for (int c = vs * 16; c < vs * 16 + 16; c++) {
            float x = s_in[c];
            float4 w = ((const float4*)(Wl2 + c * FF))[fq];
            acc2.x = fmaf(x, w.x, acc2.x); acc2.y = fmaf(x, w.y, acc2.y);
            acc2.z = fmaf(x, w.z, acc2.z); acc2.w = fmaf(x, w.w, acc2.w);
        }
        s_part[vs * 32 + fq] = acc2;
        __syncthreads();
        if (tid < 32) {
            float4 o = ((const float4*)bl2)[tid];
            #pragma unroll
            for (int p = 0; p < 8; p++) {
                float4 a = s_part[p * 32 + tid];
                o.x += a.x; o.y += a.y; o.z += a.z; o.w += a.w;
            }
            ((float4*)(g_lang + r * FF))[tid] = o;
            __threadfence();
        }
        __syncthreads();
        if (tid == 0) atomicAdd(&g_c2, 1);

    } else if (bid < 192) {
        // ================= tiled feat encoder + attention ==================
        int p0 = (bid - 64) * 32;
        int pg = tid & 7, fg = tid >> 3;   // 8 point-groups x 32 f-groups

        // ---- GEMM1: H = X @ W1 + b1 (packed f32x2 accumulators) ----
        float4 bv = ((const float4*)b1)[fg];
        ull accL[4], accH[4];
        #pragma unroll
        for (int i = 0; i < 4; i++) { accL[i] = pk2(bv.x, bv.y); accH[i] = pk2(bv.z, bv.w); }

        for (int kc = 0; kc < 8; kc++) {
            int k0 = kc * 32;
            {   // stage X chunk transposed: sXT[k][p]
                int p = tid >> 3, kq = (tid & 7) * 4;
                float4 xv = *(const float4*)&X[(p0 + p) * FV + k0 + kq];
                s[OFF_XT + (kq + 0) * 36 + p] = xv.x;
                s[OFF_XT + (kq + 1) * 36 + p] = xv.y;
                s[OFF_XT + (kq + 2) * 36 + p] = xv.z;
                s[OFF_XT + (kq + 3) * 36 + p] = xv.w;
            }
            {   // stage W1 chunk: sW[k][f]
                const float4* wg = (const float4*)(W1 + k0 * FF);
                float4* ws = (float4*)(s + OFF_W);
                #pragma unroll
                for (int rr = 0; rr < 4; rr++) ws[rr * 256 + tid] = wg[rr * 256 + tid];
            }
            __syncthreads();
            #pragma unroll 8
            for (int kk = 0; kk < 32; kk++) {
                float4 xv = *(const float4*)&s[OFF_XT + kk * 36 + pg * 4];
                ulonglong2 wv = *(const ulonglong2*)&s[OFF_W + kk * FF + fg * 4];
                ull a0 = pk2(xv.x, xv.x), a1 = pk2(xv.y, xv.y);
                ull a2 = pk2(xv.z, xv.z), a3 = pk2(xv.w, xv.w);
                accL[0] = fma2(a0, wv.x, accL[0]); accH[0] = fma2(a0, wv.y, accH[0]);
                accL[1] = fma2(a1, wv.x, accL[1]); accH[1] = fma2(a1, wv.y, accH[1]);
                accL[2] = fma2(a2, wv.x, accL[2]); accH[2] = fma2(a2, wv.y, accH[2]);
                accL[3] = fma2(a3, wv.x, accL[3]); accH[3] = fma2(a3, wv.y, accH[3]);
            }
            __syncthreads();
        }
        // write H^T: sHT[f][p]
        #pragma unroll
        for (int i = 0; i < 4; i++) {
            float2 lo = upk(accL[i]), hi = upk(accH[i]);
            int p = pg * 4 + i;
            s[OFF_HT + (fg * 4 + 0) * 36 + p] = lo.x;
            s[OFF_HT + (fg * 4 + 1) * 36 + p] = lo.y;
            s[OFF_HT + (fg * 4 + 2) * 36 + p] = hi.x;
            s[OFF_HT + (fg * 4 + 3) * 36 + p] = hi.y;
        }
        __syncthreads();

        // ---- LayerNorm + ReLU, in place on sHT (warp handles 4 points) ----
        {
            float g0 = lng[lane], g1 = lng[lane + 32], g2 = lng[lane + 64], g3 = lng[lane + 96];
            float c0 = lnb[lane], c1 = lnb[lane + 32], c2 = lnb[lane + 64], c3 = lnb[lane + 96];
            #pragma unroll
            for (int pp = 0; pp < 4; pp++) {
                int p = warp * 4 + pp;
                float v0 = s[OFF_HT + lane * 36 + p];
                float v1 = s[OFF_HT + (lane + 32) * 36 + p];
                float v2 = s[OFF_HT + (lane + 64) * 36 + p];
                float v3 = s[OFF_HT + (lane + 96) * 36 + p];
                float sm = v0 + v1 + v2 + v3;
                #pragma unroll
                for (int o = 16; o; o >>= 1) sm += __shfl_xor_sync(~0u, sm, o);
                float mean = sm * (1.f / FF);
                float d0 = v0 - mean, d1 = v1 - mean, d2 = v2 - mean, d3 = v3 - mean;
                float q = d0 * d0 + d1 * d1 + d2 * d2 + d3 * d3;
                #pragma unroll
                for (int o = 16; o; o >>= 1) q += __shfl_xor_sync(~0u, q, o);
                float inv = rsqrtf(q * (1.f / FF) + 1e-5f);
                s[OFF_HT + lane * 36 + p]        = fmaxf(fmaf(d0 * inv, g0, c0), 0.f);
                s[OFF_HT + (lane + 32) * 36 + p] = fmaxf(fmaf(d1 * inv, g1, c1), 0.f);
                s[OFF_HT + (lane + 64) * 36 + p] = fmaxf(fmaf(d2 * inv, g2, c2), 0.f);
                s[OFF_HT + (lane + 96) * 36 + p] = fmaxf(fmaf(d3 * inv, g3, c3), 0.f);
            }
        }

        // ---- GEMM2: O = relu(H) @ W2 + b2 ----
        float4 b2v = ((const float4*)b2)[fg];
        ull oL[4], oH[4];
        #pragma unroll
        for (int i = 0; i < 4; i++) { oL[i] = pk2(b2v.x, b2v.y); oH[i] = pk2(b2v.z, b2v.w); }
        for (int kc = 0; kc < 4; kc++) {
            int k0 = kc * 32;
            {   // stage W2 chunk
                const float4* wg = (const float4*)(W2 + k0 * FF);
                float4* ws = (float4*)(s + OFF_W);
                #pragma unroll
                for (int rr = 0; rr < 4; rr++) ws[rr * 256 + tid] = wg[rr * 256 + tid];
            }
            __syncthreads();
            #pragma unroll 8
            for (int kk = 0; kk < 32; kk++) {
                float4 xv = *(const float4*)&s[OFF_HT + (k0 + kk) * 36 + pg * 4];
                ulonglong2 wv = *(const ulonglong2*)&s[OFF_W + kk * FF + fg * 4];
                ull a0 = pk2(xv.x, xv.x), a1 = pk2(xv.y, xv.y);
                ull a2 = pk2(xv.z, xv.z), a3 = pk2(xv.w, xv.w);
                oL[0] = fma2(a0, wv.x, oL[0]); oH[0] = fma2(a0, wv.y, oH[0]);
                oL[1] = fma2(a1, wv.x, oL[1]); oH[1] = fma2(a1, wv.y, oH[1]);
                oL[2] = fma2(a2, wv.x, oL[2]); oH[2] = fma2(a2, wv.y, oH[2]);
                oL[3] = fma2(a3, wv.x, oL[3]); oH[3] = fma2(a3, wv.y, oH[3]);
            }
            __syncthreads();
        }

        // ---- epilogue: store g_feats + O tile, wait for lang, atten -------
        int b = p0 >> 10;
        #pragma unroll
        for (int i = 0; i < 4; i++) {
            float2 lo = upk(oL[i]), hi = upk(oH[i]);
            float4 ov = make_float4(lo.x, lo.y, hi.x, hi.y);
            int p = pg * 4 + i;
            ((float4*)&g_feats[(p0 + p) * FF])[fg] = ov;
            *(float4*)&s[OFF_O + p * 132 + fg * 4] = ov;
        }
        if (tid == 0) { while (atomicAdd(&g_c2, 0) < 64) __nanosleep(64); }
        __syncthreads();
        __threadfence();
        {   // stage lang[b]: 2048 floats
            const float4* lg = (const float4*)(g_lang + b * LL * FF);
            float4* ls = (float4*)(s + OFF_LG);
            ls[tid] = lg[tid];
            ls[tid + 256] = lg[tid + 256];
        }
        __syncthreads();
        #pragma unroll
        for (int pp = 0; pp < 4; pp++) {
            int p = warp * 4 + pp;
            float4 ov = *(const float4*)&s[OFF_O + p * 132 + lane * 4];
            #pragma unroll
            for (int l = 0; l < LL; l++) {
                float4 lv = *(const float4*)&s[OFF_LG + l * FF + lane * 4];
                float d = ov.x * lv.x + ov.y * lv.y + ov.z * lv.z + ov.w * lv.w;
                #pragma unroll
                for (int o = 16; o; o >>= 1) d += __shfl_xor_sync(~0u, d, o);
                if (lane == 0) g_atten[(p0 + p) * LL + l] = d;
            }
        }
    } else {
        // ======================= batched kNN ===============================
        int kb = bid - 192;               // 0..511
        int bq = kb >> 7;                 // batch (128 blocks per batch)
        int lq = (kb & 127) * 8 + warp;   // local query id
        int q  = bq * NPER + lq;          // global query id

        float* s_x = s;
        float* s_y = s + 1024;
        float* s_z = s + 2048;
        for (int t = tid; t < NPER; t += 256) {
            int g = (bq * NPER + t) * 3;
            s_x[t] = xyz[g]; s_y[t] = xyz[g + 1]; s_z[t] = xyz[g + 2];
        }
        __syncthreads();

        float qx = s_x[lq], qy = s_y[lq], qz = s_z[lq];
        float d[32];
        #pragma unroll
        for (int m = 0; m < 32; m++) {
            int j = m * 32 + lane;        // conflict-free, index-ordered per lane
            float dx = qx - s_x[j], dy = qy - s_y[j], dz = qz - s_z[j];
            d[m] = dx * dx + dy * dy + dz * dz;
        }

        unsigned sel = 0u;
        for (int r = 0; r < KNN; r++) {
            float mv = 3.4e38f; int mm = 0;
            #pragma unroll
            for (int m = 0; m < 32; m++) {
                bool ok = !((sel >> m) & 1u) && (d[m] < mv);
                if (ok) { mv = d[m]; mm = m; }
            }
            int gi = mm * 32 + lane;
            #pragma unroll
            for (int o = 16; o; o >>= 1) {
                float ov = __shfl_xor_sync(0xffffffffu, mv, o);
                int   oi = __shfl_xor_sync(0xffffffffu, gi, o);
                if (ov < mv || (ov == mv && oi < gi)) { mv = ov; gi = oi; }
            }
            if ((gi & 31) == lane) sel |= 1u << (gi >> 5);
            if (lane == 0) g_knn[q * KNN + r] = bq * NPER + gi;
        }
    }
}

// ---------------- kernel 4: edges, register-micro-tiled (4j x 4f / thread) ---
__global__ __launch_bounds__(FF) void k_edge(
    const float* __restrict__ xyz,
    const float* __restrict__ mask,
    const float* __restrict__ Wr1, const float* __restrict__ br1,
    const float* __restrict__ Wr2, const float* __restrict__ br2,
    float* __restrict__ out)
{
    int i = blockIdx.x, tid = threadIdx.x;
    __shared__ int s_nb[KNN];
    __shared__ __align__(16) float s_aT[LL][16];     // [l][j] attention
    __shared__ __align__(16) float s_hidT[64][20];   // [h][j] rel hidden (pad 20)
    __shared__ __align__(16) float s_geo[KNN][12];   // geo, float4-padded rows

    if (tid < KNN) s_nb[tid] = g_knn[i * KNN + tid];
    __syncthreads();

    {   // load neighbor logits transposed: 256 values, 2 per thread
        int j = tid >> 4, l = tid & 15;
        s_aT[l][j]     = g_atten[s_nb[j] * LL + l];
        s_aT[l][j + 8] = g_atten[s_nb[j + 8] * LL + l];
    }
    __syncthreads();

    // phase A: per-l softmax over the 16 neighbors, * mask[i,l]
    if (tid < LL) {
        int l = tid;
        float m = -3.4e38f;
        #pragma unroll
        for (int j = 0; j < KNN; j++) m = fmaxf(m, s_aT[l][j]);
        float e[KNN]; float sum = 0.f;
        #pragma unroll
        for (int j = 0; j < KNN; j++) { e[j] = __expf(s_aT[l][j] - m); sum += e[j]; }
        float scale = __fdividef(mask[i * LL + l], sum);
        #pragma unroll
        for (int j = 0; j < KNN; j++) s_aT[l][j] = e[j] * scale;
    }
    __syncthreads();

    // phase B: per-edge renormalization over l + geometric features
    if (tid < KNN) {
        int j = tid;
        float ssum = 0.f;
        #pragma unroll
        for (int l = 0; l < LL; l++) ssum += s_aT[l][j];
        float inv = __fdividef(1.f, ssum + 1e-7f);
        #pragma unroll
        for (int l = 0; l < LL; l++) s_aT[l][j] *= inv;

        int nj = s_nb[j];
        float xi0 = xyz[i * 3], xi1 = xyz[i * 3 + 1], xi2 = xyz[i * 3 + 2];
        float xj0 = xyz[nj * 3], xj1 = xyz[nj * 3 + 1], xj2 = xyz[nj * 3 + 2];
        float d0 = xi0 - xj0, d1 = xi1 - xj1, d2 = xi2 - xj2;
        float nr = sqrtf(d0 * d0 + d1 * d1 + d2 * d2 + 1e-12f);
        s_geo[j][0] = xi0; s_geo[j][1] = xi1; s_geo[j][2] = xi2;
        s_geo[j][3] = xj0; s_geo[j][4] = xj1; s_geo[j][5] = xj2;
        s_geo[j][6] = d0;  s_geo[j][7] = d1;  s_geo[j][8] = d2;
        s_geo[j][9] = nr;  s_geo[j][10] = 0.f; s_geo[j][11] = 0.f;
    }
    __syncthreads();

    // rel MLP hidden: thread = (hg 0..31 -> 2 h, jq 0..3 -> 4 j), packed f32x2
    {
        int hg = tid >> 2, jq = tid & 3;
        ull wv[10];
        #pragma unroll
        for (int dd = 0; dd < 10; dd++) wv[dd] = *(const ull*)&Wr1[dd * 64 + hg * 2];
        float2 bb = *(const float2*)&br1[hg * 2];
        ull bpk = pk2(bb.x, bb.y);
        float r0[4], r1[4];
        #pragma unroll
        for (int jj = 0; jj < 4; jj++) {
            int j = jq * 4 + jj;
            float4 ga = *(const float4*)&s_geo[j][0];
            float4 gb = *(const float4*)&s_geo[j][4];
            float2 gc = *(const float2*)&s_geo[j][8];
            ull a = bpk;
            a = fma2(pk2(ga.x, ga.x), wv[0], a);
            a = fma2(pk2(ga.y, ga.y), wv[1], a);
            a = fma2(pk2(ga.z, ga.z), wv[2], a);
            a = fma2(pk2(ga.w, ga.w), wv[3], a);
            a = fma2(pk2(gb.x, gb.x), wv[4], a);
            a = fma2(pk2(gb.y, gb.y), wv[5], a);
            a = fma2(pk2(gb.z, gb.z), wv[6], a);
            a = fma2(pk2(gb.w, gb.w), wv[7], a);
            a = fma2(pk2(gc.x, gc.x), wv[8], a);
            a = fma2(pk2(gc.y, gc.y), wv[9], a);
            float2 f2 = upk(a);
            r0[jj] = fmaxf(f2.x, 0.f);
            r1[jj] = fmaxf(f2.y, 0.f);
        }
        *(float4*)&s_hidT[hg * 2][jq * 4]     = make_float4(r0[0], r0[1], r0[2], r0[3]);
        *(float4*)&s_hidT[hg * 2 + 1][jq * 4] = make_float4(r1[0], r1[1], r1[2], r1[3]);
    }
    __syncthreads();

    int jg = tid & 3, fg = tid >> 2;    // 4 j-groups x 32 f-groups

    // ew[4j][4f] = hid @ Wr2 + br2  (packed f32x2)
    float4 b2v = ((const float4*)br2)[fg];
    ull ewL[4], ewH[4];
    #pragma unroll
    for (int jj = 0; jj < 4; jj++) { ewL[jj] = pk2(b2v.x, b2v.y); ewH[jj] = pk2(b2v.z, b2v.w); }
    #pragma unroll 8
    for (int k = 0; k < 64; k++) {
        float4 hv = *(const float4*)&s_hidT[k][jg * 4];
        ulonglong2 wv = *(const ulonglong2*)&Wr2[k * FF + fg * 4];
        ull a0 = pk2(hv.x, hv.x), a1 = pk2(hv.y, hv.y);
        ull a2 = pk2(hv.z, hv.z), a3 = pk2(hv.w, hv.w);
        ewL[0] = fma2(a0, wv.x, ewL[0]); ewH[0] = fma2(a0, wv.y, ewH[0]);
        ewL[1] = fma2(a1, wv.x, ewL[1]); ewH[1] = fma2(a1, wv.y, ewH[1]);
        ewL[2] = fma2(a2, wv.x, ewL[2]); ewH[2] = fma2(a2, wv.y, ewH[2]);
        ewL[3] = fma2(a3, wv.x, ewL[3]); ewH[3] = fma2(a3, wv.y, ewH[3]);
    }

    // ctx[4j][4f] = att @ lang_b  (packed f32x2)
    ull cxL[4] = {0ull, 0ull, 0ull, 0ull}, cxH[4] = {0ull, 0ull, 0ull, 0ull};
    const float* lb = g_lang + (i >> 10) * LL * FF;
    #pragma unroll
    for (int l = 0; l < LL; l++) {
        float4 av = *(const float4*)&s_aT[l][jg * 4];
        ulonglong2 lv = *(const ulonglong2*)&lb[l * FF + fg * 4];
        ull a0 = pk2(av.x, av.x), a1 = pk2(av.y, av.y);
        ull a2 = pk2(av.z, av.z), a3 = pk2(av.w, av.w);
        cxL[0] = fma2(a0, lv.x, cxL[0]); cxH[0] = fma2(a0, lv.y, cxH[0]);
        cxL[1] = fma2(a1, lv.x, cxL[1]); cxH[1] = fma2(a1, lv.y, cxH[1]);
        cxL[2] = fma2(a2, lv.x, cxL[2]); cxH[2] = fma2(a2, lv.y, cxH[2]);
        cxL[3] = fma2(a3, lv.x, cxL[3]); cxH[3] = fma2(a3, lv.y, cxH[3]);
    }

    // msg = feats[col] * ctx * ew, partial-sum over this thread's 4 j
    float4 res = make_float4(0.f, 0.f, 0.f, 0.f);
    #pragma unroll
    for (int jj = 0; jj < 4; jj++) {
        int nj = s_nb[jg * 4 + jj];
        float4 fv = ((const float4*)&g_feats[nj * FF])[fg];
        float2 eL = upk(ewL[jj]), eH = upk(ewH[jj]);
        float2 cL = upk(cxL[jj]), cH = upk(cxH[jj]);
        res.x = fmaf(fv.x * cL.x, eL.x, res.x);
        res.y = fmaf(fv.y * cL.y, eL.y, res.y);
        res.z = fmaf(fv.z * cH.x, eH.x, res.z);
        res.w = fmaf(fv.w * cH.y, eH.y, res.w);
    }
    // reduce the 4 jg-threads sharing this f-quad (xor 1, 2 within 4-group)
    #pragma unroll
    for (int o = 1; o <= 2; o <<= 1) {
        res.x += __shfl_xor_sync(~0u, res.x, o);
        res.y += __shfl_xor_sync(~0u, res.y, o);
        res.z += __shfl_xor_sync(~0u, res.z, o);
        res.w += __shfl_xor_sync(~0u, res.w, o);
    }
    if (jg == 0) {
        float4 rv = ((const float4*)&g_feats[i * FF])[fg];
        res.x += rv.x; res.y += rv.y; res.z += rv.z; res.w += rv.w;
        ((float4*)&out[i * FF])[fg] = res;
    }
}

// ---------------- launch ------------------------------------------------------
extern "C" void kernel_launch(void* const* d_in, const int* in_sizes, int n_in,
                              void* d_out, int out_size)
{
    const float* xyz   = (const float*)d_in[0];
    const float* feats = (const float*)d_in[2];
    const float* lft   = (const float*)d_in[3];
    const float* mask  = (const float*)d_in[4];
    const float* W1    = (const float*)d_in[5];
    const float* b1    = (const float*)d_in[6];
    const float* lng   = (const float*)d_in[7];
    const float* lnb   = (const float*)d_in[8];
    const float* W2    = (const float*)d_in[9];
    const float* b2    = (const float*)d_in[10];
    const float* Wl1   = (const float*)d_in[11];
    const float* bl1   = (const float*)d_in[12];
    const float* bng   = (const float*)d_in[13];
    const float* bnb   = (const float*)d_in[14];
    const float* Wl2   = (const float*)d_in[15];
    const float* bl2   = (const float*)d_in[16];
    const float* Wr1   = (const float*)d_in[17];
    const float* br1   = (const float*)d_in[18];
    const float* Wr2   = (const float*)d_in[19];
    const float* br2   = (const float*)d_in[20];
    float* out = (float*)d_out;

    k_reset<<<1, 32>>>();
    k_mega<<<704, 256>>>(xyz, feats, W1, b1, lng, lnb, W2, b2,
                         lft, Wl1, bl1, bng, bnb, Wl2, bl2);
    k_edge<<<NPTS, FF>>>(xyz, mask, Wr1, br1, Wr2, br2, out);
}